// round 10
// baseline (speedup 1.0000x reference)
#include <cuda_runtime.h>

#define D 256
#define NMAX 65536
#define EMAX 1048576

// Scratch (static __device__ — no allocations allowed)
__device__ float g_al[NMAX];
__device__ float g_ar[NMAX];
__device__ int   g_cnt[NMAX];
__device__ int   g_off[NMAX + 1];
__device__ int   g_pos[NMAX];
__device__ int2  g_edge[EMAX];   // .x = src, .y = coef bits

// K1: per-node dots a_l, a_r (warp per node) + zero counters
__global__ void node_pre_kernel(const float* __restrict__ node,
                                const float* __restrict__ att_l,
                                const float* __restrict__ att_r, int N) {
    __shared__ float s_l[D];
    __shared__ float s_r[D];
    int tid = threadIdx.x;
    s_l[tid] = att_l[tid];
    s_r[tid] = att_r[tid];
    __syncthreads();

    int warp = tid >> 5, lane = tid & 31;
    int n = blockIdx.x * 8 + warp;
    if (n >= N) return;

    const float4* row = (const float4*)(node + (size_t)n * D);
    const float4* sl4 = (const float4*)s_l;
    const float4* sr4 = (const float4*)s_r;

    float sl = 0.f, sr = 0.f;
#pragma unroll
    for (int i = 0; i < 2; i++) {
        int idx = lane + 32 * i;
        float4 v = row[idx];
        float4 al = sl4[idx];
        float4 ar = sr4[idx];
        sl += v.x * al.x + v.y * al.y + v.z * al.z + v.w * al.w;
        sr += v.x * ar.x + v.y * ar.y + v.z * ar.z + v.w * ar.w;
    }
#pragma unroll
    for (int o = 16; o > 0; o >>= 1) {
        sl += __shfl_xor_sync(0xffffffffu, sl, o);
        sr += __shfl_xor_sync(0xffffffffu, sr, o);
    }
    if (lane == 0) {
        g_al[n] = sl;
        g_ar[n] = sr;
        g_cnt[n] = 0;
    }
}

// K2: in-degree histogram (vectorized index reads)
__global__ void hist_kernel(const int* __restrict__ ei, int E) {
    int i = blockIdx.x * blockDim.x + threadIdx.x;
    int nv = E >> 2;
    if (i < nv) {
        int4 d4 = __ldg((const int4*)(ei + E) + i);
        atomicAdd(&g_cnt[d4.x], 1);
        atomicAdd(&g_cnt[d4.y], 1);
        atomicAdd(&g_cnt[d4.z], 1);
        atomicAdd(&g_cnt[d4.w], 1);
    }
    if (i < (E & 3)) {
        atomicAdd(&g_cnt[__ldg(ei + E + nv * 4 + i)], 1);
    }
}

// K3: exclusive scan of g_cnt -> g_off (and g_pos). Single block, 1024 threads.
__global__ void scan_kernel(int N, int E) {
    __shared__ int ssum[1024];
    int t = threadIdx.x;
    int chunk = (N + 1023) / 1024;
    int base = t * chunk;
    int s = 0;
    for (int i = 0; i < chunk; i++) {
        int idx = base + i;
        if (idx < N) s += g_cnt[idx];
    }
    ssum[t] = s;
    __syncthreads();
    for (int o = 1; o < 1024; o <<= 1) {
        int v = 0;
        if (t >= o) v = ssum[t - o];
        __syncthreads();
        if (t >= o) ssum[t] += v;
        __syncthreads();
    }
    int run = (t == 0) ? 0 : ssum[t - 1];
    for (int i = 0; i < chunk; i++) {
        int idx = base + i;
        if (idx < N) {
            g_off[idx] = run;
            g_pos[idx] = run;
            run += g_cnt[idx];
        }
    }
    if (t == 0) g_off[N] = E;
}

// K4: scatter edges into CSR slots. 4 edges per thread via vectorized loads:
// four independent latency chains (al/ar loads, ATOMGs) per thread.
__global__ void scatter_kernel(const int* __restrict__ ei,
                               const float* __restrict__ ew, int E) {
    int i = blockIdx.x * blockDim.x + threadIdx.x;
    int nv = E >> 2;
    if (i < nv) {
        int4   s4 = __ldg((const int4*)ei + i);
        int4   d4 = __ldg((const int4*)(ei + E) + i);
        float4 w4 = __ldg((const float4*)ew + i);
        // 8 independent scalar loads
        float al0 = __ldg(&g_al[s4.x]), ar0 = __ldg(&g_ar[d4.x]);
        float al1 = __ldg(&g_al[s4.y]), ar1 = __ldg(&g_ar[d4.y]);
        float al2 = __ldg(&g_al[s4.z]), ar2 = __ldg(&g_ar[d4.z]);
        float al3 = __ldg(&g_al[s4.w]), ar3 = __ldg(&g_ar[d4.w]);
        float c0 = tanhf(al0 + ar0) * w4.x;
        float c1 = tanhf(al1 + ar1) * w4.y;
        float c2 = tanhf(al2 + ar2) * w4.z;
        float c3 = tanhf(al3 + ar3) * w4.w;
        // 4 independent atomics
        int p0 = atomicAdd(&g_pos[d4.x], 1);
        int p1 = atomicAdd(&g_pos[d4.y], 1);
        int p2 = atomicAdd(&g_pos[d4.z], 1);
        int p3 = atomicAdd(&g_pos[d4.w], 1);
        g_edge[p0] = make_int2(s4.x, __float_as_int(c0));
        g_edge[p1] = make_int2(s4.y, __float_as_int(c1));
        g_edge[p2] = make_int2(s4.z, __float_as_int(c2));
        g_edge[p3] = make_int2(s4.w, __float_as_int(c3));
    }
    if (i < (E & 3)) {
        int idx = nv * 4 + i;
        int s = __ldg(ei + idx);
        int d = __ldg(ei + E + idx);
        float coef = tanhf(__ldg(&g_al[s]) + __ldg(&g_ar[d])) * __ldg(ew + idx);
        int p = atomicAdd(&g_pos[d], 1);
        g_edge[p] = make_int2(s, __float_as_int(coef));
    }
}

// K5: warp-per-dst gather with edge-descriptor prefetch (1 iter ahead):
// row loads issue immediately each iteration; next-edge latency overlaps
// with row wait + FMAs. Fused 0.1*node_0 + LayerNorm + ReLU epilogue.
__global__ void agg_ln_kernel(const float* __restrict__ node,
                              const float* __restrict__ node0,
                              const float* __restrict__ w,
                              const float* __restrict__ b,
                              float* __restrict__ out, int N) {
    int warp = threadIdx.x >> 5, lane = threadIdx.x & 31;
    int n = blockIdx.x * 8 + warp;
    if (n >= N) return;

    int k0 = __ldg(&g_off[n]);
    int k1 = __ldg(&g_off[n + 1]);

    float4 a0 = make_float4(0.f, 0.f, 0.f, 0.f);
    float4 a1 = make_float4(0.f, 0.f, 0.f, 0.f);

    int nb = (k1 - k0) >> 2;     // full 4-edge batches
    int e = k0;
    if (nb > 0) {
        // prologue: load first batch of edge descriptors
        int2 c0 = __ldg(g_edge + e);
        int2 c1 = __ldg(g_edge + e + 1);
        int2 c2 = __ldg(g_edge + e + 2);
        int2 c3 = __ldg(g_edge + e + 3);
        for (int bi = 0; bi < nb; bi++) {
            int ebase = k0 + bi * 4;
            bool more = (bi + 1 < nb);
            // prefetch next batch (independent of current rows)
            int2 p0, p1, p2, p3;
            if (more) {
                p0 = __ldg(g_edge + ebase + 4);
                p1 = __ldg(g_edge + ebase + 5);
                p2 = __ldg(g_edge + ebase + 6);
                p3 = __ldg(g_edge + ebase + 7);
            }
            // row loads: addresses ready at iteration start
            const float4* r0 = (const float4*)(node + (size_t)c0.x * D);
            const float4* r1 = (const float4*)(node + (size_t)c1.x * D);
            const float4* r2 = (const float4*)(node + (size_t)c2.x * D);
            const float4* r3 = (const float4*)(node + (size_t)c3.x * D);
            float4 v0 = __ldg(r0 + lane), u0 = __ldg(r0 + lane + 32);
            float4 v1 = __ldg(r1 + lane), u1 = __ldg(r1 + lane + 32);
            float4 v2 = __ldg(r2 + lane), u2 = __ldg(r2 + lane + 32);
            float4 v3 = __ldg(r3 + lane), u3 = __ldg(r3 + lane + 32);
            float cf0 = __int_as_float(c0.y);
            float cf1 = __int_as_float(c1.y);
            float cf2 = __int_as_float(c2.y);
            float cf3 = __int_as_float(c3.y);
            a0.x += v0.x * cf0; a0.y += v0.y * cf0; a0.z += v0.z * cf0; a0.w += v0.w * cf0;
            a1.x += u0.x * cf0; a1.y += u0.y * cf0; a1.z += u0.z * cf0; a1.w += u0.w * cf0;
            a0.x += v1.x * cf1; a0.y += v1.y * cf1; a0.z += v1.z * cf1; a0.w += v1.w * cf1;
            a1.x += u1.x * cf1; a1.y += u1.y * cf1; a1.z += u1.z * cf1; a1.w += u1.w * cf1;
            a0.x += v2.x * cf2; a0.y += v2.y * cf2; a0.z += v2.z * cf2; a0.w += v2.w * cf2;
            a1.x += u2.x * cf2; a1.y += u2.y * cf2; a1.z += u2.z * cf2; a1.w += u2.w * cf2;
            a0.x += v3.x * cf3; a0.y += v3.y * cf3; a0.z += v3.z * cf3; a0.w += v3.w * cf3;
            a1.x += u3.x * cf3; a1.y += u3.y * cf3; a1.z += u3.z * cf3; a1.w += u3.w * cf3;
            if (more) { c0 = p0; c1 = p1; c2 = p2; c3 = p3; }
        }
        e = k0 + nb * 4;
    }
    for (; e < k1; e++) {
        int2 e0 = __ldg(g_edge + e);
        float cf = __int_as_float(e0.y);
        const float4* r0 = (const float4*)(node + (size_t)e0.x * D);
        float4 v0 = __ldg(r0 + lane), u0 = __ldg(r0 + lane + 32);
        a0.x += v0.x * cf; a0.y += v0.y * cf; a0.z += v0.z * cf; a0.w += v0.w * cf;
        a1.x += u0.x * cf; a1.y += u0.y * cf; a1.z += u0.z * cf; a1.w += u0.w * cf;
    }

    // + 0.1 * node_0
    const float4* row0 = (const float4*)(node0 + (size_t)n * D);
    float4 z0 = __ldg(row0 + lane), z1 = __ldg(row0 + lane + 32);
    a0.x += 0.1f * z0.x; a0.y += 0.1f * z0.y; a0.z += 0.1f * z0.z; a0.w += 0.1f * z0.w;
    a1.x += 0.1f * z1.x; a1.y += 0.1f * z1.y; a1.z += 0.1f * z1.z; a1.w += 0.1f * z1.w;

    // LayerNorm over D=256 + ReLU
    float sum = a0.x + a0.y + a0.z + a0.w + a1.x + a1.y + a1.z + a1.w;
    float sq  = a0.x * a0.x + a0.y * a0.y + a0.z * a0.z + a0.w * a0.w
              + a1.x * a1.x + a1.y * a1.y + a1.z * a1.z + a1.w * a1.w;
#pragma unroll
    for (int o = 16; o > 0; o >>= 1) {
        sum += __shfl_xor_sync(0xffffffffu, sum, o);
        sq  += __shfl_xor_sync(0xffffffffu, sq, o);
    }
    float mean = sum * (1.0f / D);
    float var  = sq * (1.0f / D) - mean * mean;
    float inv  = rsqrtf(var + 1e-5f);

    const float4* w4 = (const float4*)w;
    const float4* b4 = (const float4*)b;
    float4* orow = (float4*)(out + (size_t)n * D);
#pragma unroll
    for (int i = 0; i < 2; i++) {
        int idx = lane + 32 * i;
        float4 v = (i == 0) ? a0 : a1;
        float4 ww = __ldg(w4 + idx);
        float4 bb = __ldg(b4 + idx);
        float4 r;
        r.x = fmaxf((v.x - mean) * inv * ww.x + bb.x, 0.0f);
        r.y = fmaxf((v.y - mean) * inv * ww.y + bb.y, 0.0f);
        r.z = fmaxf((v.z - mean) * inv * ww.z + bb.z, 0.0f);
        r.w = fmaxf((v.w - mean) * inv * ww.w + bb.w, 0.0f);
        orow[idx] = r;
    }
}

extern "C" void kernel_launch(void* const* d_in, const int* in_sizes, int n_in,
                              void* d_out, int out_size) {
    const float* node  = (const float*)d_in[0];
    const float* node0 = (const float*)d_in[1];
    const int*   ei    = (const int*)d_in[2];
    const float* ew    = (const float*)d_in[3];
    // d_in[4] = batch_ptr (unused in node-mode LayerNorm)
    const float* att_l = (const float*)d_in[5];
    const float* att_r = (const float*)d_in[6];
    const float* lnw   = (const float*)d_in[7];
    const float* lnb   = (const float*)d_in[8];
    float* out = (float*)d_out;

    int N = in_sizes[0] / D;
    int E = in_sizes[3];

    node_pre_kernel<<<(N + 7) / 8, 256>>>(node, att_l, att_r, N);
    hist_kernel<<<((E >> 2) + 255) / 256, 256>>>(ei, E);
    scan_kernel<<<1, 1024>>>(N, E);
    scatter_kernel<<<((E >> 2) + 255) / 256, 256>>>(ei, ew, E);
    agg_ln_kernel<<<(N + 7) / 8, 256>>>(node, node0, lnw, lnb, out, N);
}

// round 16
// speedup vs baseline: 1.2072x; 1.2072x over previous
#include <cuda_runtime.h>

#define D 256
#define NMAX 65536
#define EMAX 1048576

// Scratch (static __device__ — no allocations allowed; zero-init at load)
__device__ float g_al[NMAX];
__device__ float g_ar[NMAX];
__device__ int   g_cnt[NMAX];      // always zero outside [hist, scan) window
__device__ int   g_off[NMAX + 1];
__device__ int   g_pos[NMAX];
__device__ int2  g_edge[EMAX];     // .x = src, .y = coef bits

// K1 (fused): blocks [0, blocksA) do per-node dots; blocks [blocksA, ...) do
// the in-degree histogram (independent work, one launch).
__global__ void pre_hist_kernel(const float* __restrict__ node,
                                const float* __restrict__ att_l,
                                const float* __restrict__ att_r,
                                const int* __restrict__ ei,
                                int N, int E, int blocksA) {
    if ((int)blockIdx.x < blocksA) {
        __shared__ float s_l[D];
        __shared__ float s_r[D];
        int tid = threadIdx.x;
        s_l[tid] = att_l[tid];
        s_r[tid] = att_r[tid];
        __syncthreads();

        int warp = tid >> 5, lane = tid & 31;
        int n = blockIdx.x * 8 + warp;
        if (n >= N) return;

        const float4* row = (const float4*)(node + (size_t)n * D);
        const float4* sl4 = (const float4*)s_l;
        const float4* sr4 = (const float4*)s_r;

        float sl = 0.f, sr = 0.f;
#pragma unroll
        for (int i = 0; i < 2; i++) {
            int idx = lane + 32 * i;
            float4 v = row[idx];
            float4 al = sl4[idx];
            float4 ar = sr4[idx];
            sl += v.x * al.x + v.y * al.y + v.z * al.z + v.w * al.w;
            sr += v.x * ar.x + v.y * ar.y + v.z * ar.z + v.w * ar.w;
        }
#pragma unroll
        for (int o = 16; o > 0; o >>= 1) {
            sl += __shfl_xor_sync(0xffffffffu, sl, o);
            sr += __shfl_xor_sync(0xffffffffu, sr, o);
        }
        if (lane == 0) {
            g_al[n] = sl;
            g_ar[n] = sr;
        }
    } else {
        // histogram part: 4 dst indices per thread (vectorized)
        int i = (blockIdx.x - blocksA) * blockDim.x + threadIdx.x;
        int nv = E >> 2;
        if (i < nv) {
            int4 d4 = __ldg((const int4*)(ei + E) + i);
            atomicAdd(&g_cnt[d4.x], 1);
            atomicAdd(&g_cnt[d4.y], 1);
            atomicAdd(&g_cnt[d4.z], 1);
            atomicAdd(&g_cnt[d4.w], 1);
        }
        if (i < (E & 3)) {
            atomicAdd(&g_cnt[__ldg(ei + E + nv * 4 + i)], 1);
        }
    }
}

// K2: exclusive scan of g_cnt -> g_off (and g_pos), vectorized int4 reads.
// Two passes over g_cnt (second pass is L2-hot); re-zeros g_cnt after
// consuming it (replay determinism for the fused hist).
// Single block, 1024 threads; 13 int4/thread covers 53248 >= N entries.
__global__ void __launch_bounds__(1024) scan_kernel(int N, int E) {
    __shared__ int ssum[1024];
    const int CH4 = 13;                 // int4 chunks per thread
    int t = threadIdx.x;
    int4* cnt4 = (int4*)g_cnt;
    int base4 = t * CH4;

    // phase 1: per-thread sum (no caching -> low register pressure)
    int s = 0;
#pragma unroll
    for (int i = 0; i < CH4; i++) {
        int4 v = cnt4[base4 + i];
        s += v.x + v.y + v.z + v.w;
    }
    ssum[t] = s;
    __syncthreads();
    for (int o = 1; o < 1024; o <<= 1) {
        int v = 0;
        if (t >= o) v = ssum[t - o];
        __syncthreads();
        if (t >= o) ssum[t] += v;
        __syncthreads();
    }
    int run = (t == 0) ? 0 : ssum[t - 1];
    // phase 2: re-read (L2-hot), emit offsets, re-zero
#pragma unroll
    for (int i = 0; i < CH4; i++) {
        int4 v = cnt4[base4 + i];
        int idx = (base4 + i) * 4;
        int c[4] = {v.x, v.y, v.z, v.w};
#pragma unroll
        for (int j = 0; j < 4; j++) {
            if (idx + j < N) {
                g_off[idx + j] = run;
                g_pos[idx + j] = run;
                run += c[j];
            }
        }
        cnt4[base4 + i] = make_int4(0, 0, 0, 0);   // re-zero for next replay
    }
    if (t == 0) g_off[N] = E;
}

// K3: scatter edges into CSR slots; compute coef here; single packed 8B store.
// (1 edge/thread — best measured config; high occupancy hides the chain.)
__global__ void scatter_kernel(const int* __restrict__ ei,
                               const float* __restrict__ ew, int E) {
    int i = blockIdx.x * blockDim.x + threadIdx.x;
    if (i >= E) return;
    int s = __ldg(ei + i);
    int d = __ldg(ei + E + i);
    float coef = tanhf(__ldg(&g_al[s]) + __ldg(&g_ar[d])) * __ldg(ew + i);
    int p = atomicAdd(&g_pos[d], 1);
    g_edge[p] = make_int2(s, __float_as_int(coef));
}

// K4: warp-per-dst gather, 4-edge batches, register accumulation,
// fused 0.1*node_0 + LayerNorm + ReLU epilogue. Single store per output row.
__global__ void agg_ln_kernel(const float* __restrict__ node,
                              const float* __restrict__ node0,
                              const float* __restrict__ w,
                              const float* __restrict__ b,
                              float* __restrict__ out, int N) {
    int warp = threadIdx.x >> 5, lane = threadIdx.x & 31;
    int n = blockIdx.x * 8 + warp;
    if (n >= N) return;

    int k0 = __ldg(&g_off[n]);
    int k1 = __ldg(&g_off[n + 1]);

    float4 a0 = make_float4(0.f, 0.f, 0.f, 0.f);
    float4 a1 = make_float4(0.f, 0.f, 0.f, 0.f);

    int e = k0;
    for (; e + 3 < k1; e += 4) {
        int2 e0 = __ldg(g_edge + e);
        int2 e1 = __ldg(g_edge + e + 1);
        int2 e2 = __ldg(g_edge + e + 2);
        int2 e3 = __ldg(g_edge + e + 3);
        const float4* r0 = (const float4*)(node + (size_t)e0.x * D);
        const float4* r1 = (const float4*)(node + (size_t)e1.x * D);
        const float4* r2 = (const float4*)(node + (size_t)e2.x * D);
        const float4* r3 = (const float4*)(node + (size_t)e3.x * D);
        float4 v0 = __ldg(r0 + lane), u0 = __ldg(r0 + lane + 32);
        float4 v1 = __ldg(r1 + lane), u1 = __ldg(r1 + lane + 32);
        float4 v2 = __ldg(r2 + lane), u2 = __ldg(r2 + lane + 32);
        float4 v3 = __ldg(r3 + lane), u3 = __ldg(r3 + lane + 32);
        float c0 = __int_as_float(e0.y);
        float c1 = __int_as_float(e1.y);
        float c2 = __int_as_float(e2.y);
        float c3 = __int_as_float(e3.y);
        a0.x += v0.x * c0; a0.y += v0.y * c0; a0.z += v0.z * c0; a0.w += v0.w * c0;
        a1.x += u0.x * c0; a1.y += u0.y * c0; a1.z += u0.z * c0; a1.w += u0.w * c0;
        a0.x += v1.x * c1; a0.y += v1.y * c1; a0.z += v1.z * c1; a0.w += v1.w * c1;
        a1.x += u1.x * c1; a1.y += u1.y * c1; a1.z += u1.z * c1; a1.w += u1.w * c1;
        a0.x += v2.x * c2; a0.y += v2.y * c2; a0.z += v2.z * c2; a0.w += v2.w * c2;
        a1.x += u2.x * c2; a1.y += u2.y * c2; a1.z += u2.z * c2; a1.w += u2.w * c2;
        a0.x += v3.x * c3; a0.y += v3.y * c3; a0.z += v3.z * c3; a0.w += v3.w * c3;
        a1.x += u3.x * c3; a1.y += u3.y * c3; a1.z += u3.z * c3; a1.w += u3.w * c3;
    }
    for (; e < k1; e++) {
        int2 e0 = __ldg(g_edge + e);
        float cf = __int_as_float(e0.y);
        const float4* r0 = (const float4*)(node + (size_t)e0.x * D);
        float4 v0 = __ldg(r0 + lane), u0 = __ldg(r0 + lane + 32);
        a0.x += v0.x * cf; a0.y += v0.y * cf; a0.z += v0.z * cf; a0.w += v0.w * cf;
        a1.x += u0.x * cf; a1.y += u0.y * cf; a1.z += u0.z * cf; a1.w += u0.w * cf;
    }

    // + 0.1 * node_0
    const float4* row0 = (const float4*)(node0 + (size_t)n * D);
    float4 z0 = __ldg(row0 + lane), z1 = __ldg(row0 + lane + 32);
    a0.x += 0.1f * z0.x; a0.y += 0.1f * z0.y; a0.z += 0.1f * z0.z; a0.w += 0.1f * z0.w;
    a1.x += 0.1f * z1.x; a1.y += 0.1f * z1.y; a1.z += 0.1f * z1.z; a1.w += 0.1f * z1.w;

    // LayerNorm over D=256 + ReLU
    float sum = a0.x + a0.y + a0.z + a0.w + a1.x + a1.y + a1.z + a1.w;
    float sq  = a0.x * a0.x + a0.y * a0.y + a0.z * a0.z + a0.w * a0.w
              + a1.x * a1.x + a1.y * a1.y + a1.z * a1.z + a1.w * a1.w;
#pragma unroll
    for (int o = 16; o > 0; o >>= 1) {
        sum += __shfl_xor_sync(0xffffffffu, sum, o);
        sq  += __shfl_xor_sync(0xffffffffu, sq, o);
    }
    float mean = sum * (1.0f / D);
    float var  = sq * (1.0f / D) - mean * mean;
    float inv  = rsqrtf(var + 1e-5f);

    const float4* w4 = (const float4*)w;
    const float4* b4 = (const float4*)b;
    float4* orow = (float4*)(out + (size_t)n * D);
#pragma unroll
    for (int i = 0; i < 2; i++) {
        int idx = lane + 32 * i;
        float4 v = (i == 0) ? a0 : a1;
        float4 ww = __ldg(w4 + idx);
        float4 bb = __ldg(b4 + idx);
        float4 r;
        r.x = fmaxf((v.x - mean) * inv * ww.x + bb.x, 0.0f);
        r.y = fmaxf((v.y - mean) * inv * ww.y + bb.y, 0.0f);
        r.z = fmaxf((v.z - mean) * inv * ww.z + bb.z, 0.0f);
        r.w = fmaxf((v.w - mean) * inv * ww.w + bb.w, 0.0f);
        orow[idx] = r;
    }
}

extern "C" void kernel_launch(void* const* d_in, const int* in_sizes, int n_in,
                              void* d_out, int out_size) {
    const float* node  = (const float*)d_in[0];
    const float* node0 = (const float*)d_in[1];
    const int*   ei    = (const int*)d_in[2];
    const float* ew    = (const float*)d_in[3];
    // d_in[4] = batch_ptr (unused in node-mode LayerNorm)
    const float* att_l = (const float*)d_in[5];
    const float* att_r = (const float*)d_in[6];
    const float* lnw   = (const float*)d_in[7];
    const float* lnb   = (const float*)d_in[8];
    float* out = (float*)d_out;

    int N = in_sizes[0] / D;
    int E = in_sizes[3];

    int blocksA = (N + 7) / 8;
    int blocksB = ((E >> 2) + 255) / 256;
    pre_hist_kernel<<<blocksA + blocksB, 256>>>(node, att_l, att_r, ei, N, E, blocksA);
    scan_kernel<<<1, 1024>>>(N, E);
    scatter_kernel<<<(E + 255) / 256, 256>>>(ei, ew, E);
    agg_ln_kernel<<<(N + 7) / 8, 256>>>(node, node0, lnw, lnb, out, N);
}